// round 1
// baseline (speedup 1.0000x reference)
#include <cuda_runtime.h>
#include <cuda_bf16.h>
#include <stdint.h>
#include <math.h>

#define L_NUM 4
#define B_NUM 256
#define H_NUM 65536
#define NSPLIT 16
#define KC (H_NUM / NSPLIT)   /* 4096 K per CTA */
#define BK 32
#define NIT (KC / BK)         /* 128 iterations */
#define BM 128
#define BN 128
#define SROW 40               /* padded smem row stride in bf16 (32 + 8) */
#define EPS_F 1e-8f

/* ---------------- scratch (static __device__ — no allocs allowed) -------- */
__device__ __nv_bfloat16 g_xbf[(size_t)L_NUM * B_NUM * H_NUM];          /* 134 MB */
__device__ float g_rn[L_NUM * B_NUM];                                   /* 1/norm */
__device__ float g_part[(size_t)NSPLIT * L_NUM * B_NUM * B_NUM];        /* 16 MB  */
__device__ float g_v[L_NUM * B_NUM];                                    /* log ratios */

/* ---------------- helpers ------------------------------------------------ */
__device__ __forceinline__ unsigned int pack2(float a, float b) {
    __nv_bfloat162 p = __floats2bfloat162_rn(a, b);
    return *reinterpret_cast<unsigned int*>(&p);
}
__device__ __forceinline__ uint32_t cvta_s(const void* p) {
    return (uint32_t)__cvta_generic_to_shared(p);
}
__device__ __forceinline__ void cp16(uint32_t sa, const void* g) {
    asm volatile("cp.async.cg.shared.global [%0], [%1], 16;\n" :: "r"(sa), "l"(g));
}
__device__ __forceinline__ void ldm4(uint32_t* r, const void* p) {
    uint32_t a = cvta_s(p);
    asm volatile("ldmatrix.sync.aligned.m8n8.x4.shared.b16 {%0,%1,%2,%3}, [%4];\n"
                 : "=r"(r[0]), "=r"(r[1]), "=r"(r[2]), "=r"(r[3]) : "r"(a));
}
__device__ __forceinline__ void mma_bf16(float* c, const uint32_t* a, const uint32_t* b) {
    asm volatile(
        "mma.sync.aligned.m16n8k16.row.col.f32.bf16.bf16.f32 "
        "{%0,%1,%2,%3}, {%4,%5,%6,%7}, {%8,%9}, {%0,%1,%2,%3};\n"
        : "+f"(c[0]), "+f"(c[1]), "+f"(c[2]), "+f"(c[3])
        : "r"(a[0]), "r"(a[1]), "r"(a[2]), "r"(a[3]), "r"(b[0]), "r"(b[1]));
}

/* ---------------- kernel A: fp32 -> bf16 convert + row sumsq ------------- */
__global__ __launch_bounds__(256) void k_convert(const float* __restrict__ in) {
    const int row = blockIdx.x;                  /* l*B + b */
    const size_t base = (size_t)row * H_NUM;
    const float4* __restrict__ src = reinterpret_cast<const float4*>(in + base);
    uint4* __restrict__ dst = reinterpret_cast<uint4*>(g_xbf + base);
    const int t = threadIdx.x;
    float ss = 0.f;
    #pragma unroll 4
    for (int i = 0; i < H_NUM / (256 * 8); ++i) {
        const int e8 = i * 256 + t;
        float4 f0 = src[2 * e8 + 0];
        float4 f1 = src[2 * e8 + 1];
        ss = fmaf(f0.x, f0.x, ss); ss = fmaf(f0.y, f0.y, ss);
        ss = fmaf(f0.z, f0.z, ss); ss = fmaf(f0.w, f0.w, ss);
        ss = fmaf(f1.x, f1.x, ss); ss = fmaf(f1.y, f1.y, ss);
        ss = fmaf(f1.z, f1.z, ss); ss = fmaf(f1.w, f1.w, ss);
        uint4 o;
        o.x = pack2(f0.x, f0.y); o.y = pack2(f0.z, f0.w);
        o.z = pack2(f1.x, f1.y); o.w = pack2(f1.z, f1.w);
        dst[e8] = o;
    }
    __shared__ float red[256];
    red[t] = ss;
    __syncthreads();
    for (int s = 128; s > 0; s >>= 1) {
        if (t < s) red[t] += red[t + s];
        __syncthreads();
    }
    if (t == 0) g_rn[row] = 1.f / fmaxf(sqrtf(red[0]), 1e-12f);
}

/* ---------------- kernel B: split-K Gram GEMM (bf16 mma.sync) ------------ */
/* grid = L * 4tiles * NSPLIT = 256 CTAs; CTA = 128x128 C-tile over KC=4096  */
__global__ __launch_bounds__(256, 2) void k_gemm() {
    __shared__ __align__(128) __nv_bfloat16 As[2][BM * SROW];
    __shared__ __align__(128) __nv_bfloat16 Bs[2][BN * SROW];

    const int cta   = blockIdx.x;
    const int layer = cta >> 6;          /* 64 CTAs per layer */
    const int rem   = cta & 63;
    const int split = rem >> 2;
    const int tm    = (rem >> 1) & 1;
    const int tn    = rem & 1;

    const __nv_bfloat16* __restrict__ Ag =
        g_xbf + (size_t)(layer * B_NUM + tm * BM) * H_NUM + (size_t)split * KC;
    const __nv_bfloat16* __restrict__ Bg =
        g_xbf + (size_t)(layer * B_NUM + tn * BN) * H_NUM + (size_t)split * KC;

    const int t    = threadIdx.x;
    const int lane = t & 31;
    const int warp = t >> 5;
    const int wm   = warp >> 2;      /* 0..1 : 64-row strip */
    const int wn   = warp & 3;       /* 0..3 : 32-col strip */

    /* per-thread fill coords: 2 x 16B segments per operand per BK=32 tile */
    const int s0 = t,        r0 = s0 >> 2, c0 = (s0 & 3) * 8;
    const int s1 = t + 256,  r1 = s1 >> 2, c1 = (s1 & 3) * 8;

    float acc[4][4][4];
    #pragma unroll
    for (int i = 0; i < 4; ++i)
        #pragma unroll
        for (int j = 0; j < 4; ++j)
            #pragma unroll
            for (int k = 0; k < 4; ++k) acc[i][j][k] = 0.f;

    /* prefetch iter 0 */
    cp16(cvta_s(&As[0][r0 * SROW + c0]), Ag + (size_t)r0 * H_NUM + c0);
    cp16(cvta_s(&As[0][r1 * SROW + c1]), Ag + (size_t)r1 * H_NUM + c1);
    cp16(cvta_s(&Bs[0][r0 * SROW + c0]), Bg + (size_t)r0 * H_NUM + c0);
    cp16(cvta_s(&Bs[0][r1 * SROW + c1]), Bg + (size_t)r1 * H_NUM + c1);
    asm volatile("cp.async.commit_group;\n");

    int buf = 0;
    #pragma unroll 1
    for (int it = 0; it < NIT; ++it) {
        if (it + 1 < NIT) {
            const int kb = (it + 1) * BK;
            const int nb = buf ^ 1;
            cp16(cvta_s(&As[nb][r0 * SROW + c0]), Ag + (size_t)r0 * H_NUM + kb + c0);
            cp16(cvta_s(&As[nb][r1 * SROW + c1]), Ag + (size_t)r1 * H_NUM + kb + c1);
            cp16(cvta_s(&Bs[nb][r0 * SROW + c0]), Bg + (size_t)r0 * H_NUM + kb + c0);
            cp16(cvta_s(&Bs[nb][r1 * SROW + c1]), Bg + (size_t)r1 * H_NUM + kb + c1);
            asm volatile("cp.async.commit_group;\n");
            asm volatile("cp.async.wait_group 1;\n");
        } else {
            asm volatile("cp.async.wait_group 0;\n");
        }
        __syncthreads();

        const __nv_bfloat16* Ab = As[buf];
        const __nv_bfloat16* Bb = Bs[buf];
        const int g  = lane >> 3;
        const int rr = lane & 7;

        #pragma unroll
        for (int ks = 0; ks < 2; ++ks) {
            const int k16 = ks * 16;
            uint32_t a[4][4], b[4][2];
            /* A fragments: 4 x m16 blocks; ldmatrix lane map:
               g0: rows+0..7 @k, g1: rows+8..15 @k, g2: rows+0..7 @k+8, g3: rows+8..15 @k+8 */
            const int arow = (g & 1) * 8 + rr;
            const int acol = k16 + (g >> 1) * 8;
            #pragma unroll
            for (int mi = 0; mi < 4; ++mi)
                ldm4(a[mi], Ab + (wm * 64 + mi * 16 + arow) * SROW + acol);
            /* B fragments: 4 x n8 blocks via 2 ldmatrix.x4:
               g0: n+0..7 @k, g1: n+0..7 @k+8, g2: n+8..15 @k, g3: n+8..15 @k+8 */
            const int brow = (g >> 1) * 8 + rr;
            const int bcol = k16 + (g & 1) * 8;
            #pragma unroll
            for (int nb2 = 0; nb2 < 2; ++nb2) {
                uint32_t r4[4];
                ldm4(r4, Bb + (wn * 32 + nb2 * 16 + brow) * SROW + bcol);
                b[nb2 * 2 + 0][0] = r4[0]; b[nb2 * 2 + 0][1] = r4[1];
                b[nb2 * 2 + 1][0] = r4[2]; b[nb2 * 2 + 1][1] = r4[3];
            }
            #pragma unroll
            for (int mi = 0; mi < 4; ++mi)
                #pragma unroll
                for (int ni = 0; ni < 4; ++ni)
                    mma_bf16(acc[mi][ni], a[mi], b[ni]);
        }
        __syncthreads();
        buf ^= 1;
    }

    /* store partial tile (no atomics: deterministic split-K buffer) */
    float* __restrict__ outp =
        g_part + ((size_t)(split * L_NUM + layer)) * (B_NUM * B_NUM);
    const int qr = lane >> 2;
    const int qc = (lane & 3) * 2;
    #pragma unroll
    for (int mi = 0; mi < 4; ++mi) {
        #pragma unroll
        for (int ni = 0; ni < 4; ++ni) {
            const int row = tm * BM + wm * 64 + mi * 16 + qr;
            const int col = tn * BN + wn * 32 + ni * 8 + qc;
            float2 v0 = make_float2(acc[mi][ni][0], acc[mi][ni][1]);
            float2 v1 = make_float2(acc[mi][ni][2], acc[mi][ni][3]);
            *reinterpret_cast<float2*>(outp + (size_t)row * B_NUM + col) = v0;
            *reinterpret_cast<float2*>(outp + (size_t)(row + 8) * B_NUM + col) = v1;
        }
    }
}

/* ---------------- kernel C: epilogue per (l, b) row ---------------------- */
__global__ __launch_bounds__(256) void k_epi(const int* __restrict__ ttw) {
    const int lb = blockIdx.x;
    const int l = lb >> 8;
    const int b = lb & 255;
    const int c = threadIdx.x;

    /* detect task_type element width: int64 iff all odd 32-bit words are 0
       (values are in [0,16), so int64 upper words are always 0; for int32
       data the odd words are random 0..15 -> P(all zero) ~ 16^-128)        */
    __shared__ int s64;
    if (c == 0) s64 = 1;
    __syncthreads();
    if (c < 128 && ttw[2 * c + 1] != 0) s64 = 0;
    __syncthreads();
    const int is64 = s64;
    const int ttb = is64 ? ttw[2 * b] : ttw[b];
    const int ttc = is64 ? ttw[2 * c] : ttw[c];

    float sum = 0.f;
    #pragma unroll
    for (int s = 0; s < NSPLIT; ++s)
        sum += g_part[(((size_t)s * L_NUM + l) * B_NUM + b) * B_NUM + c];

    const float dot = sum * g_rn[lb] * g_rn[l * B_NUM + c];
    const float d2  = fmaxf(2.f - 2.f * dot, 0.f);   /* sq_b = sq_c = 1 */
    const float w   = expf(-2.f * d2);               /* exp(-d2 / 0.5)  */
    const float wp  = (ttb == ttc && c != b) ? w : 0.f;

    __shared__ float ra[256], rb[256];
    ra[c] = wp; rb[c] = w;
    __syncthreads();
    for (int s = 128; s > 0; s >>= 1) {
        if (c < s) { ra[c] += ra[c + s]; rb[c] += rb[c + s]; }
        __syncthreads();
    }
    if (c == 0) g_v[lb] = logf((ra[0] + EPS_F) / (rb[0] + EPS_F));
}

/* ---------------- kernel D: final deterministic reduce ------------------- */
__global__ __launch_bounds__(256) void k_final(float* __restrict__ out) {
    const int t = threadIdx.x;
    float s = 0.f;
    for (int i = t; i < L_NUM * B_NUM; i += 256) s += g_v[i];
    __shared__ float red[256];
    red[t] = s;
    __syncthreads();
    for (int k = 128; k > 0; k >>= 1) {
        if (t < k) red[t] += red[t + k];
        __syncthreads();
    }
    /* loss = sum_l ( -mean_b v ) / L * 0.2 = -sum(v) * 0.2 / (B*L) */
    if (t == 0) out[0] = -red[0] * (0.2f / (float)(L_NUM * B_NUM));
}

/* ---------------- launch -------------------------------------------------- */
extern "C" void kernel_launch(void* const* d_in, const int* in_sizes, int n_in,
                              void* d_out, int out_size) {
    const float* hs = (const float*)d_in[0];
    const int*   tt = (const int*)d_in[1];
    (void)in_sizes; (void)n_in; (void)out_size;

    k_convert<<<L_NUM * B_NUM, 256>>>(hs);
    k_gemm<<<L_NUM * 4 * NSPLIT, 256>>>();
    k_epi<<<L_NUM * B_NUM, 256>>>(tt);
    k_final<<<1, 256>>>((float*)d_out);
}

// round 3
// speedup vs baseline: 1.2288x; 1.2288x over previous
#include <cuda_runtime.h>
#include <cuda_bf16.h>
#include <stdint.h>
#include <math.h>

#define L_NUM 4
#define B_NUM 256
#define H_NUM 65536
#define NSPLIT 32
#define KC (H_NUM / NSPLIT)   /* 2048 K per CTA */
#define BK 32
#define NIT (KC / BK)         /* 64 iterations */
#define BM 128
#define SROW 40               /* padded smem row stride in bf16 (32 + 8) */
#define EPS_F 1e-8f

/* ---------------- scratch ------------------------------------------------ */
__device__ float g_part[(size_t)NSPLIT * L_NUM * B_NUM * B_NUM];   /* 32 MB */
__device__ float g_rn[L_NUM * B_NUM];
__device__ float g_v[L_NUM * B_NUM];
__device__ int   g_ctr;

/* ---------------- helpers ------------------------------------------------ */
__device__ __forceinline__ unsigned int pack2(float a, float b) {
    __nv_bfloat162 p = __floats2bfloat162_rn(a, b);
    return *reinterpret_cast<unsigned int*>(&p);
}
__device__ __forceinline__ uint32_t cvta_s(const void* p) {
    return (uint32_t)__cvta_generic_to_shared(p);
}
__device__ __forceinline__ void ldm4(uint32_t* r, const void* p) {
    uint32_t a = cvta_s(p);
    asm volatile("ldmatrix.sync.aligned.m8n8.x4.shared.b16 {%0,%1,%2,%3}, [%4];\n"
                 : "=r"(r[0]), "=r"(r[1]), "=r"(r[2]), "=r"(r[3]) : "r"(a));
}
__device__ __forceinline__ void mma_bf16(float* c, const uint32_t* a, const uint32_t* b) {
    asm volatile(
        "mma.sync.aligned.m16n8k16.row.col.f32.bf16.bf16.f32 "
        "{%0,%1,%2,%3}, {%4,%5,%6,%7}, {%8,%9}, {%0,%1,%2,%3};\n"
        : "+f"(c[0]), "+f"(c[1]), "+f"(c[2]), "+f"(c[3])
        : "r"(a[0]), "r"(a[1]), "r"(a[2]), "r"(a[3]), "r"(b[0]), "r"(b[1]));
}

/* ---------------- fused convert + split-K SYRK --------------------------- */
/* grid = 4 layers x 3 tiles x 32 splits = 384 CTAs.                         */
/* tiles: 0 -> (tm=0,tn=0), 1 -> (0,1) + transposed store, 2 -> (1,1).      */
__global__ __launch_bounds__(256, 2) void k_gemm(const float* __restrict__ hs) {
    __shared__ __align__(128) __nv_bfloat16 As[2][BM * SROW];
    __shared__ __align__(128) __nv_bfloat16 Bs[2][BM * SROW];

    const int cta    = blockIdx.x;
    const int split  = cta & 31;
    const int tmp    = cta >> 5;
    const int layer  = tmp / 3;
    const int tileid = tmp - layer * 3;
    const int tm     = (tileid == 2) ? 1 : 0;
    const int tn     = (tileid == 0) ? 0 : 1;

    const float* __restrict__ Ag =
        hs + (size_t)(layer * B_NUM + tm * BM) * H_NUM + (size_t)split * KC;
    const float* __restrict__ Bg =
        hs + (size_t)(layer * B_NUM + tn * BM) * H_NUM + (size_t)split * KC;

    const int t    = threadIdx.x;
    const int lane = t & 31;
    const int warp = t >> 5;
    const int wm   = warp >> 2;      /* 0..1 : 64-row strip  */
    const int wn   = warp & 3;       /* 0..3 : 32-col strip  */

    /* producer coords: each thread fills 4 rows x one 4-float segment */
    const int prow = t >> 3;         /* 0..31, rows prow + 32*j        */
    const int pseg = t & 7;          /* 4-float column segment         */

    float acc[4][4][4];
    #pragma unroll
    for (int i = 0; i < 4; ++i)
        #pragma unroll
        for (int j = 0; j < 4; ++j)
            #pragma unroll
            for (int k = 0; k < 4; ++k) acc[i][j][k] = 0.f;

    /* ---- prologue: fill stage 0 ---- */
    {
        float4 fa[4], fb[4];
        #pragma unroll
        for (int j = 0; j < 4; ++j) {
            const size_t go = (size_t)(prow + 32 * j) * H_NUM + pseg * 4;
            fa[j] = *reinterpret_cast<const float4*>(Ag + go);
            fb[j] = *reinterpret_cast<const float4*>(Bg + go);
        }
        #pragma unroll
        for (int j = 0; j < 4; ++j) {
            const int so = (prow + 32 * j) * SROW + pseg * 4;
            *reinterpret_cast<uint2*>(&As[0][so]) =
                make_uint2(pack2(fa[j].x, fa[j].y), pack2(fa[j].z, fa[j].w));
            *reinterpret_cast<uint2*>(&Bs[0][so]) =
                make_uint2(pack2(fb[j].x, fb[j].y), pack2(fb[j].z, fb[j].w));
        }
    }
    __syncthreads();

    #pragma unroll 1
    for (int it = 0; it < NIT; ++it) {
        const int buf = it & 1;

        /* issue next-stage global loads early (hide under MMA) */
        float4 fa[4], fb[4];
        const bool more = (it + 1) < NIT;
        if (more) {
            const int kb = (it + 1) * BK;
            #pragma unroll
            for (int j = 0; j < 4; ++j) {
                const size_t go = (size_t)(prow + 32 * j) * H_NUM + kb + pseg * 4;
                fa[j] = *reinterpret_cast<const float4*>(Ag + go);
                fb[j] = *reinterpret_cast<const float4*>(Bg + go);
            }
        }

        /* ---- MMA on current buf ---- */
        const __nv_bfloat16* Ab = As[buf];
        const __nv_bfloat16* Bb = Bs[buf];
        const int g  = lane >> 3;
        const int rr = lane & 7;

        #pragma unroll
        for (int ks = 0; ks < 2; ++ks) {
            const int k16 = ks * 16;
            uint32_t a[4][4], b[4][2];
            const int arow = (g & 1) * 8 + rr;
            const int acol = k16 + (g >> 1) * 8;
            #pragma unroll
            for (int mi = 0; mi < 4; ++mi)
                ldm4(a[mi], Ab + (wm * 64 + mi * 16 + arow) * SROW + acol);
            const int brow = (g >> 1) * 8 + rr;
            const int bcol = k16 + (g & 1) * 8;
            #pragma unroll
            for (int nb2 = 0; nb2 < 2; ++nb2) {
                uint32_t r4[4];
                ldm4(r4, Bb + (wn * 32 + nb2 * 16 + brow) * SROW + bcol);
                b[nb2 * 2 + 0][0] = r4[0]; b[nb2 * 2 + 0][1] = r4[1];
                b[nb2 * 2 + 1][0] = r4[2]; b[nb2 * 2 + 1][1] = r4[3];
            }
            #pragma unroll
            for (int mi = 0; mi < 4; ++mi)
                #pragma unroll
                for (int ni = 0; ni < 4; ++ni)
                    mma_bf16(acc[mi][ni], a[mi], b[ni]);
        }

        /* ---- convert + store next stage ---- */
        if (more) {
            const int nb = buf ^ 1;
            #pragma unroll
            for (int j = 0; j < 4; ++j) {
                const int so = (prow + 32 * j) * SROW + pseg * 4;
                *reinterpret_cast<uint2*>(&As[nb][so]) =
                    make_uint2(pack2(fa[j].x, fa[j].y), pack2(fa[j].z, fa[j].w));
                *reinterpret_cast<uint2*>(&Bs[nb][so]) =
                    make_uint2(pack2(fb[j].x, fb[j].y), pack2(fb[j].z, fb[j].w));
            }
        }
        __syncthreads();
    }

    /* ---- store partial tile (+ mirrored tile for tileid==1) ---- */
    float* __restrict__ outp =
        g_part + ((size_t)(split * L_NUM + layer) << 16);
    const int qr = lane >> 2;
    const int qc = (lane & 3) * 2;
    #pragma unroll
    for (int mi = 0; mi < 4; ++mi) {
        #pragma unroll
        for (int ni = 0; ni < 4; ++ni) {
            const int row = tm * BM + wm * 64 + mi * 16 + qr;
            const int col = tn * BM + wn * 32 + ni * 8 + qc;
            *reinterpret_cast<float2*>(outp + ((size_t)row << 8) + col) =
                make_float2(acc[mi][ni][0], acc[mi][ni][1]);
            *reinterpret_cast<float2*>(outp + ((size_t)(row + 8) << 8) + col) =
                make_float2(acc[mi][ni][2], acc[mi][ni][3]);
            if (tileid == 1) {           /* mirror into (1,0) block */
                outp[((size_t)col << 8) + row]           = acc[mi][ni][0];
                outp[((size_t)(col + 1) << 8) + row]     = acc[mi][ni][1];
                outp[((size_t)col << 8) + row + 8]       = acc[mi][ni][2];
                outp[((size_t)(col + 1) << 8) + row + 8] = acc[mi][ni][3];
            }
        }
    }
}

/* ---------------- norms from Gram diagonal ------------------------------- */
__global__ __launch_bounds__(256) void k_diag() {
    const int l = blockIdx.x;
    const int c = threadIdx.x;
    float s = 0.f;
    #pragma unroll
    for (int sp = 0; sp < NSPLIT; ++sp)
        s += g_part[((size_t)(sp * L_NUM + l) << 16) + c * 257];
    g_rn[l * B_NUM + c] = 1.f / fmaxf(sqrtf(s), 1e-12f);
}

/* ---------------- epilogue + fused final reduce -------------------------- */
__global__ __launch_bounds__(256) void k_epi(const int* __restrict__ ttw,
                                             float* __restrict__ out) {
    const int lb = blockIdx.x;
    const int l = lb >> 8;
    const int b = lb & 255;
    const int c = threadIdx.x;

    /* int64 vs int32 task_type detection (values in [0,16)) */
    __shared__ int s64;
    if (c == 0) s64 = 1;
    __syncthreads();
    if (c < 128 && ttw[2 * c + 1] != 0) s64 = 0;
    __syncthreads();
    const int is64 = s64;
    const int ttb = is64 ? ttw[2 * b] : ttw[b];
    const int ttc = is64 ? ttw[2 * c] : ttw[c];

    float sum = 0.f;
    #pragma unroll
    for (int sp = 0; sp < NSPLIT; ++sp)
        sum += g_part[((size_t)(sp * L_NUM + l) << 16) + (b << 8) + c];

    const float dot = sum * g_rn[l * B_NUM + b] * g_rn[l * B_NUM + c];
    const float d2  = fmaxf(2.f - 2.f * dot, 0.f);
    const float w   = expf(-2.f * d2);
    const float wp  = (ttb == ttc && c != b) ? w : 0.f;

    __shared__ float ra[256], rb[256];
    ra[c] = wp; rb[c] = w;
    __syncthreads();
    for (int s = 128; s > 0; s >>= 1) {
        if (c < s) { ra[c] += ra[c + s]; rb[c] += rb[c + s]; }
        __syncthreads();
    }
    if (c == 0) g_v[lb] = logf((ra[0] + EPS_F) / (rb[0] + EPS_F));

    /* last-block final reduce (deterministic fixed-order sum) */
    __shared__ int lastp;
    __threadfence();
    if (c == 0) {
        int t = atomicAdd(&g_ctr, 1);
        lastp = (t == (L_NUM * B_NUM - 1));
    }
    __syncthreads();
    if (lastp) {
        __threadfence();
        float s = g_v[c] + g_v[c + 256] + g_v[c + 512] + g_v[c + 768];
        ra[c] = s;
        __syncthreads();
        for (int k = 128; k > 0; k >>= 1) {
            if (c < k) ra[c] += ra[c + k];
            __syncthreads();
        }
        if (c == 0) {
            out[0] = -ra[0] * (0.2f / (float)(L_NUM * B_NUM));
            g_ctr = 0;
        }
    }
}

/* ---------------- launch -------------------------------------------------- */
extern "C" void kernel_launch(void* const* d_in, const int* in_sizes, int n_in,
                              void* d_out, int out_size) {
    const float* hs = (const float*)d_in[0];
    const int*   tt = (const int*)d_in[1];
    (void)in_sizes; (void)n_in; (void)out_size;

    k_gemm<<<L_NUM * 3 * NSPLIT, 256>>>(hs);
    k_diag<<<L_NUM, 256>>>();
    k_epi<<<L_NUM * B_NUM, 256>>>(tt, (float*)d_out);
}

// round 4
// speedup vs baseline: 1.3884x; 1.1298x over previous
#include <cuda_runtime.h>
#include <cuda_bf16.h>
#include <stdint.h>
#include <math.h>

#define L_NUM 4
#define B_NUM 256
#define H_NUM 65536
#define NSPLIT 64
#define KC (H_NUM / NSPLIT)   /* 1024 K per work unit */
#define BK 32
#define NIT (KC / BK)         /* 32 iterations */
#define BM 128
#define SROW 40               /* padded smem row stride in bf16 (32 + 8) */
#define EPS_F 1e-8f

/* ---------------- scratch ------------------------------------------------ */
__device__ float g_part[(size_t)NSPLIT * L_NUM * B_NUM * B_NUM];   /* 64 MB */
__device__ float g_rn[L_NUM * B_NUM];
__device__ float g_v[L_NUM * B_NUM];
__device__ int   g_ctr;

/* ---------------- helpers ------------------------------------------------ */
__device__ __forceinline__ unsigned int pack2(float a, float b) {
    __nv_bfloat162 p = __floats2bfloat162_rn(a, b);
    return *reinterpret_cast<unsigned int*>(&p);
}
__device__ __forceinline__ uint32_t cvta_s(const void* p) {
    return (uint32_t)__cvta_generic_to_shared(p);
}
__device__ __forceinline__ void ldm4(uint32_t* r, const void* p) {
    uint32_t a = cvta_s(p);
    asm volatile("ldmatrix.sync.aligned.m8n8.x4.shared.b16 {%0,%1,%2,%3}, [%4];\n"
                 : "=r"(r[0]), "=r"(r[1]), "=r"(r[2]), "=r"(r[3]) : "r"(a));
}
__device__ __forceinline__ void mma_bf16(float* c, const uint32_t* a, const uint32_t* b) {
    asm volatile(
        "mma.sync.aligned.m16n8k16.row.col.f32.bf16.bf16.f32 "
        "{%0,%1,%2,%3}, {%4,%5,%6,%7}, {%8,%9}, {%0,%1,%2,%3};\n"
        : "+f"(c[0]), "+f"(c[1]), "+f"(c[2]), "+f"(c[3])
        : "r"(a[0]), "r"(a[1]), "r"(a[2]), "r"(a[3]), "r"(b[0]), "r"(b[1]));
}

/* ---------------- fused convert + split-K SYRK --------------------------- */
/* grid = 4 layers x 3 tiles x 64 splits = 768 CTAs.                         */
/* tiles: 0 -> (0,0) diag, 1 -> (0,1) + mirrored store, 2 -> (1,1) diag.    */
__global__ __launch_bounds__(256, 2) void k_gemm(const float* __restrict__ hs) {
    __shared__ __align__(128) __nv_bfloat16 As[2][BM * SROW];
    __shared__ __align__(128) __nv_bfloat16 Bs[2][BM * SROW];

    const int cta    = blockIdx.x;
    const int split  = cta & (NSPLIT - 1);
    const int tmp    = cta >> 6;
    const int layer  = tmp / 3;
    const int tileid = tmp - layer * 3;
    const int tm     = (tileid == 2) ? 1 : 0;
    const int tn     = (tileid == 0) ? 0 : 1;
    const bool diag  = (tileid != 1);

    const float* __restrict__ Ag =
        hs + (size_t)(layer * B_NUM + tm * BM) * H_NUM + (size_t)split * KC;
    const float* __restrict__ Bg =
        hs + (size_t)(layer * B_NUM + tn * BM) * H_NUM + (size_t)split * KC;

    const int t    = threadIdx.x;
    const int lane = t & 31;
    const int warp = t >> 5;
    const int wm   = warp >> 2;      /* 0..1 : 64-row strip  */
    const int wn   = warp & 3;       /* 0..3 : 32-col strip  */

    /* producer coords: each thread fills 4 rows x one 4-float segment */
    const int prow = t >> 3;         /* 0..31, rows prow + 32*j        */
    const int pseg = t & 7;          /* 4-float column segment         */

    float acc[4][4][4];
    #pragma unroll
    for (int i = 0; i < 4; ++i)
        #pragma unroll
        for (int j = 0; j < 4; ++j)
            #pragma unroll
            for (int k = 0; k < 4; ++k) acc[i][j][k] = 0.f;

    /* ---- prologue: fill stage 0 ---- */
    {
        float4 fa[4], fb[4];
        #pragma unroll
        for (int j = 0; j < 4; ++j) {
            const size_t go = (size_t)(prow + 32 * j) * H_NUM + pseg * 4;
            fa[j] = *reinterpret_cast<const float4*>(Ag + go);
            if (!diag) fb[j] = *reinterpret_cast<const float4*>(Bg + go);
        }
        #pragma unroll
        for (int j = 0; j < 4; ++j) {
            const int so = (prow + 32 * j) * SROW + pseg * 4;
            *reinterpret_cast<uint2*>(&As[0][so]) =
                make_uint2(pack2(fa[j].x, fa[j].y), pack2(fa[j].z, fa[j].w));
            if (!diag)
                *reinterpret_cast<uint2*>(&Bs[0][so]) =
                    make_uint2(pack2(fb[j].x, fb[j].y), pack2(fb[j].z, fb[j].w));
        }
    }
    __syncthreads();

    #pragma unroll 1
    for (int it = 0; it < NIT; ++it) {
        const int buf = it & 1;

        /* issue next-stage global loads early (hide under MMA) */
        float4 fa[4], fb[4];
        const bool more = (it + 1) < NIT;
        if (more) {
            const int kb = (it + 1) * BK;
            #pragma unroll
            for (int j = 0; j < 4; ++j) {
                const size_t go = (size_t)(prow + 32 * j) * H_NUM + kb + pseg * 4;
                fa[j] = *reinterpret_cast<const float4*>(Ag + go);
                if (!diag) fb[j] = *reinterpret_cast<const float4*>(Bg + go);
            }
        }

        /* ---- MMA on current buf ---- */
        const __nv_bfloat16* Ab = As[buf];
        const __nv_bfloat16* Bb = diag ? As[buf] : Bs[buf];
        const int g  = lane >> 3;
        const int rr = lane & 7;

        #pragma unroll
        for (int ks = 0; ks < 2; ++ks) {
            const int k16 = ks * 16;
            uint32_t a[4][4], b[4][2];
            const int arow = (g & 1) * 8 + rr;
            const int acol = k16 + (g >> 1) * 8;
            #pragma unroll
            for (int mi = 0; mi < 4; ++mi)
                ldm4(a[mi], Ab + (wm * 64 + mi * 16 + arow) * SROW + acol);
            const int brow = (g >> 1) * 8 + rr;
            const int bcol = k16 + (g & 1) * 8;
            #pragma unroll
            for (int nb2 = 0; nb2 < 2; ++nb2) {
                uint32_t r4[4];
                ldm4(r4, Bb + (wn * 32 + nb2 * 16 + brow) * SROW + bcol);
                b[nb2 * 2 + 0][0] = r4[0]; b[nb2 * 2 + 0][1] = r4[1];
                b[nb2 * 2 + 1][0] = r4[2]; b[nb2 * 2 + 1][1] = r4[3];
            }
            #pragma unroll
            for (int mi = 0; mi < 4; ++mi)
                #pragma unroll
                for (int ni = 0; ni < 4; ++ni)
                    mma_bf16(acc[mi][ni], a[mi], b[ni]);
        }

        /* ---- convert + store next stage ---- */
        if (more) {
            const int nb = buf ^ 1;
            #pragma unroll
            for (int j = 0; j < 4; ++j) {
                const int so = (prow + 32 * j) * SROW + pseg * 4;
                *reinterpret_cast<uint2*>(&As[nb][so]) =
                    make_uint2(pack2(fa[j].x, fa[j].y), pack2(fa[j].z, fa[j].w));
                if (!diag)
                    *reinterpret_cast<uint2*>(&Bs[nb][so]) =
                        make_uint2(pack2(fb[j].x, fb[j].y), pack2(fb[j].z, fb[j].w));
            }
        }
        __syncthreads();
    }

    /* ---- store partial tile (+ mirrored tile for tileid==1) ---- */
    float* __restrict__ outp =
        g_part + ((size_t)(split * L_NUM + layer) << 16);
    const int qr = lane >> 2;
    const int qc = (lane & 3) * 2;
    #pragma unroll
    for (int mi = 0; mi < 4; ++mi) {
        #pragma unroll
        for (int ni = 0; ni < 4; ++ni) {
            const int row = tm * BM + wm * 64 + mi * 16 + qr;
            const int col = tn * BM + wn * 32 + ni * 8 + qc;
            *reinterpret_cast<float2*>(outp + ((size_t)row << 8) + col) =
                make_float2(acc[mi][ni][0], acc[mi][ni][1]);
            *reinterpret_cast<float2*>(outp + ((size_t)(row + 8) << 8) + col) =
                make_float2(acc[mi][ni][2], acc[mi][ni][3]);
            if (!diag) {                 /* mirror into (1,0) block */
                outp[((size_t)col << 8) + row]           = acc[mi][ni][0];
                outp[((size_t)(col + 1) << 8) + row]     = acc[mi][ni][1];
                outp[((size_t)col << 8) + row + 8]       = acc[mi][ni][2];
                outp[((size_t)(col + 1) << 8) + row + 8] = acc[mi][ni][3];
            }
        }
    }
}

/* ---------------- norms from Gram diagonal ------------------------------- */
__global__ __launch_bounds__(256) void k_diag() {
    const int l = blockIdx.x;
    const int c = threadIdx.x;
    float s = 0.f;
    #pragma unroll
    for (int sp = 0; sp < NSPLIT; ++sp)
        s += g_part[((size_t)(sp * L_NUM + l) << 16) + c * 257];
    g_rn[l * B_NUM + c] = 1.f / fmaxf(sqrtf(s), 1e-12f);
}

/* ---------------- epilogue + fused final reduce -------------------------- */
__global__ __launch_bounds__(256) void k_epi(const int* __restrict__ ttw,
                                             float* __restrict__ out) {
    const int lb = blockIdx.x;
    const int l = lb >> 8;
    const int b = lb & 255;
    const int c = threadIdx.x;

    /* int64 vs int32 task_type detection (values in [0,16)) */
    __shared__ int s64;
    if (c == 0) s64 = 1;
    __syncthreads();
    if (c < 128 && ttw[2 * c + 1] != 0) s64 = 0;
    __syncthreads();
    const int is64 = s64;
    const int ttb = is64 ? ttw[2 * b] : ttw[b];
    const int ttc = is64 ? ttw[2 * c] : ttw[c];

    float sum = 0.f;
    #pragma unroll 8
    for (int sp = 0; sp < NSPLIT; ++sp)
        sum += g_part[((size_t)(sp * L_NUM + l) << 16) + (b << 8) + c];

    const float dot = sum * g_rn[l * B_NUM + b] * g_rn[l * B_NUM + c];
    const float d2  = fmaxf(2.f - 2.f * dot, 0.f);
    const float w   = expf(-2.f * d2);
    const float wp  = (ttb == ttc && c != b) ? w : 0.f;

    __shared__ float ra[256], rb[256];
    ra[c] = wp; rb[c] = w;
    __syncthreads();
    for (int s = 128; s > 0; s >>= 1) {
        if (c < s) { ra[c] += ra[c + s]; rb[c] += rb[c + s]; }
        __syncthreads();
    }
    if (c == 0) g_v[lb] = logf((ra[0] + EPS_F) / (rb[0] + EPS_F));

    /* last-block final reduce (deterministic fixed-order sum) */
    __shared__ int lastp;
    __threadfence();
    if (c == 0) {
        int t = atomicAdd(&g_ctr, 1);
        lastp = (t == (L_NUM * B_NUM - 1));
    }
    __syncthreads();
    if (lastp) {
        __threadfence();
        float s = g_v[c] + g_v[c + 256] + g_v[c + 512] + g_v[c + 768];
        ra[c] = s;
        __syncthreads();
        for (int k = 128; k > 0; k >>= 1) {
            if (c < k) ra[c] += ra[c + k];
            __syncthreads();
        }
        if (c == 0) {
            out[0] = -ra[0] * (0.2f / (float)(L_NUM * B_NUM));
            g_ctr = 0;
        }
    }
}

/* ---------------- launch -------------------------------------------------- */
extern "C" void kernel_launch(void* const* d_in, const int* in_sizes, int n_in,
                              void* d_out, int out_size) {
    const float* hs = (const float*)d_in[0];
    const int*   tt = (const int*)d_in[1];
    (void)in_sizes; (void)n_in; (void)out_size;

    k_gemm<<<L_NUM * 3 * NSPLIT, 256>>>(hs);
    k_diag<<<L_NUM, 256>>>();
    k_epi<<<L_NUM * B_NUM, 256>>>(tt, (float*)d_out);
}